// round 14
// baseline (speedup 1.0000x reference)
#include <cuda_runtime.h>
#include <cuda_fp16.h>
#include <math.h>
#include <stdint.h>

#define MAXN 100000
#define MAXE 320000

// ---------------- scratch (device globals; no allocs allowed) ----------------
__device__ __align__(16) float g_S0[(size_t)MAXN * 256];
__device__ __align__(16) float g_S1[(size_t)MAXN * 256];
__device__ __align__(16) float g_M [(size_t)MAXN * 512];

// fp16 state + message (single precision copy; A-side of GEMMs)
__device__ __align__(16) __half g_Sh[(size_t)MAXN * 512];
__device__ __align__(16) __half g_Mh[(size_t)MAXN * 512];

// fp16 hi/lo weight splits (natural [dout][K] layout == col-major B for mma.row.col)
__device__ __align__(16) __half g_WeI_h[6 * 4 * 256 * 512],  g_WeI_l[6 * 4 * 256 * 512];
__device__ __align__(16) __half g_WeO_h[2 * 4 * 512 * 1024], g_WeO_l[2 * 4 * 512 * 1024];
__device__ __align__(16) __half g_WdI_h[6 * 256 * 256],      g_WdI_l[6 * 256 * 256];
__device__ __align__(16) __half g_WdO_h[2 * 256 * 512],      g_WdO_l[2 * 256 * 512];

__device__ int g_typeEdges[MAXE];
__device__ int g_cnt[4], g_off[4], g_cur[4];
__device__ int g_tpos[4 * MAXN];   // per-(type,src): count, then write cursor

// ---------------- helpers ----------------
__device__ __forceinline__ uint32_t smem_u32(const void* p) {
    uint32_t a;
    asm("{ .reg .u64 t; cvta.to.shared.u64 t, %1; cvt.u32.u64 %0, t; }" : "=r"(a) : "l"(p));
    return a;
}

__device__ __forceinline__ void ldm_x4(uint32_t addr, uint32_t r[4]) {
    asm volatile("ldmatrix.sync.aligned.m8n8.x4.shared.b16 {%0,%1,%2,%3}, [%4];"
                 : "=r"(r[0]), "=r"(r[1]), "=r"(r[2]), "=r"(r[3]) : "r"(addr));
}

__device__ __forceinline__ void mma16816(float c[4], const uint32_t a[4], const uint32_t b[2]) {
    asm volatile(
        "mma.sync.aligned.m16n8k16.row.col.f32.f16.f16.f32 "
        "{%0,%1,%2,%3}, {%4,%5,%6,%7}, {%8,%9}, {%0,%1,%2,%3};"
        : "+f"(c[0]), "+f"(c[1]), "+f"(c[2]), "+f"(c[3])
        : "r"(a[0]), "r"(a[1]), "r"(a[2]), "r"(a[3]), "r"(b[0]), "r"(b[1]));
}

__device__ __forceinline__ void cpa16(uint32_t dst, const void* src) {
    asm volatile("cp.async.cg.shared.global [%0], [%1], 16;" :: "r"(dst), "l"(src) : "memory");
}

// vectorized f32 reduction (PTX ISA 8.1, sm_90+)
__device__ __forceinline__ void red2(float* addr, float a, float b) {
    asm volatile("red.global.add.v2.f32 [%0], {%1, %2};" :: "l"(addr), "f"(a), "f"(b) : "memory");
}

__device__ __forceinline__ uint32_t pk_h2(float a, float b) {
    __half2 t = __floats2half2_rn(a, b);
    return reinterpret_cast<uint32_t&>(t);
}

__device__ __forceinline__ float gelu_f(float x) {
    return 0.5f * x * (1.0f + erff(x * 0.70710678118654752f));
}

// ---------------- small utility kernels ----------------
__global__ void clear_f4_kernel(float4* p, long long n4) {
    long long i = (long long)blockIdx.x * blockDim.x + threadIdx.x;
    long long stride = (long long)gridDim.x * blockDim.x;
    float4 z = make_float4(0.f, 0.f, 0.f, 0.f);
    for (; i < n4; i += stride) p[i] = z;
}

__global__ void clear_counts_kernel() {
    int i = threadIdx.x;
    if (i < 4) { g_cnt[i] = 0; g_cur[i] = 0; }
}

__global__ void clear_tpos_kernel() {
    int i = blockIdx.x * blockDim.x + threadIdx.x;
    int stride = gridDim.x * blockDim.x;
    for (; i < 4 * MAXN; i += stride) g_tpos[i] = 0;
}

// smem block-histogram: 4 global atomics per block instead of 1 per edge
__global__ void count_types_kernel(const int* __restrict__ etype, int E) {
    __shared__ int h[4];
    if (threadIdx.x < 4) h[threadIdx.x] = 0;
    __syncthreads();
    int e = blockIdx.x * blockDim.x + threadIdx.x;
    if (e < E) atomicAdd(&h[etype[e] - 1], 1);
    __syncthreads();
    if (threadIdx.x < 4 && h[threadIdx.x] > 0) atomicAdd(&g_cnt[threadIdx.x], h[threadIdx.x]);
}

__global__ void offsets_kernel() {
    if (threadIdx.x == 0) {
        g_off[0] = 0;
        g_off[1] = g_cnt[0];
        g_off[2] = g_cnt[0] + g_cnt[1];
        g_off[3] = g_cnt[0] + g_cnt[1] + g_cnt[2];
    }
}

// per-(type, SRC) edge counts — sort key is src for A-gather locality
__global__ void count_tv_kernel(const int* __restrict__ etype, const int* __restrict__ srcA, int E) {
    int e = blockIdx.x * blockDim.x + threadIdx.x;
    if (e < E) atomicAdd(&g_tpos[(etype[e] - 1) * MAXN + srcA[e]], 1);
}

// assign each nonzero (t,s) group a contiguous slot range; g_tpos becomes the write cursor
__global__ void assign_start_kernel() {
    int i = blockIdx.x * blockDim.x + threadIdx.x;
    int stride = gridDim.x * blockDim.x;
    for (; i < 4 * MAXN; i += stride) {
        int c = g_tpos[i];
        if (c > 0) {
            int t = i / MAXN;
            g_tpos[i] = g_off[t] + atomicAdd(&g_cur[t], c);
        }
    }
}

// scatter edges sorted by (type, src): same-src edges land contiguously
__global__ void scatter_sorted_kernel(const int* __restrict__ etype, const int* __restrict__ srcA,
                                      int E) {
    int e = blockIdx.x * blockDim.x + threadIdx.x;
    if (e < E) {
        int idx = (etype[e] - 1) * MAXN + srcA[e];
        int p = atomicAdd(&g_tpos[idx], 1);
        g_typeEdges[p] = e;
    }
}

// weights: fp32 -> fp16 hi + fp16 lo (residual)
__global__ void conv_f16_kernel(const float* __restrict__ w, __half* __restrict__ hi,
                                __half* __restrict__ lo, int n) {
    int i = blockIdx.x * blockDim.x + threadIdx.x;
    if (i >= n) return;
    float x = w[i];
    __half h = __float2half_rn(x);
    hi[i] = h;
    lo[i] = __float2half_rn(x - __half2float(h));
}

// embed + fp16 split fused: one pass over the gathered rows
__global__ void embed_kernel(const float4* __restrict__ tab, const int* __restrict__ ids,
                             float4* __restrict__ outS, uint2* __restrict__ Sh, int N) {
    int idx = blockIdx.x * blockDim.x + threadIdx.x;
    if (idx >= N * 64) return;
    int node = idx >> 6, c = idx & 63;
    int r = ids[node];
    float4 v = tab[(size_t)r * 64 + c];
    outS[(size_t)node * 64 + c] = v;
    Sh[(size_t)node * 64 + c] = make_uint2(pk_h2(v.x, v.y), pk_h2(v.z, v.w));
}

// concat [save(256) | x(256)] -> 512-wide fp16 state
__global__ void concat_f16_kernel(const float4* __restrict__ save, const float4* __restrict__ x,
                                  __half* __restrict__ Sh, int N) {
    int idx = blockIdx.x * blockDim.x + threadIdx.x;
    if (idx >= N * 128) return;
    int node = idx >> 7, c = idx & 127;
    float4 v = (c < 64) ? save[(size_t)node * 64 + c] : x[(size_t)node * 64 + (c - 64)];
    ((uint2*)(Sh + (size_t)node * 512))[c] = make_uint2(pk_h2(v.x, v.y), pk_h2(v.z, v.w));
}

// gelu + layernorm; float4-vectorized; emits fp16 directly
__global__ void gelu_ln_kernel(const float4* __restrict__ M, const float4* __restrict__ s4,
                               const float4* __restrict__ b4,
                               uint2* __restrict__ Mh, int dm, int N) {
    int warp = (blockIdx.x * blockDim.x + threadIdx.x) >> 5;
    int lane = threadIdx.x & 31;
    if (warp >= N) return;
    int n4 = dm >> 2;
    int per = n4 >> 5;
    const float4* row = M + (size_t)warp * n4;
    float4 v[4];
    float sum = 0.f;
    for (int i = 0; i < per; i++) {
        float4 x = row[i * 32 + lane];
        float4 g;
        g.x = gelu_f(x.x); g.y = gelu_f(x.y); g.z = gelu_f(x.z); g.w = gelu_f(x.w);
        v[i] = g;
        sum += g.x + g.y + g.z + g.w;
    }
    #pragma unroll
    for (int o = 16; o > 0; o >>= 1) sum += __shfl_xor_sync(0xFFFFFFFF, sum, o);
    float mu = sum / (float)dm;
    float vs = 0.f;
    for (int i = 0; i < per; i++) {
        float dx = v[i].x - mu, dy = v[i].y - mu, dz = v[i].z - mu, dw = v[i].w - mu;
        vs += dx * dx + dy * dy + dz * dz + dw * dw;
    }
    #pragma unroll
    for (int o = 16; o > 0; o >>= 1) vs += __shfl_xor_sync(0xFFFFFFFF, vs, o);
    float inv = rsqrtf(vs / (float)dm + 1e-5f);
    for (int i = 0; i < per; i++) {
        int c4 = i * 32 + lane;
        float4 sv = s4[c4], bv = b4[c4];
        float y0 = (v[i].x - mu) * inv * sv.x + bv.x;
        float y1 = (v[i].y - mu) * inv * sv.y + bv.y;
        float y2 = (v[i].z - mu) * inv * sv.z + bv.z;
        float y3 = (v[i].w - mu) * inv * sv.w + bv.w;
        Mh[(size_t)warp * n4 + c4] = make_uint2(pk_h2(y0, y1), pk_h2(y2, y3));
    }
}

// ---------------- mma.sync GEMM (MODE 0: edge gather+scatter, MODE 1: dense+tanh) ----------------
// fp16 2-term: C = A_f16 @ (Bh + Bl).  CTA tile 128(M) x 256(N), K chunk 32.
// 512 threads = 16 warps (2x8), warp tile 64x32. 4-stage cp.async pipeline,
// prefetch distance 3 (load target buffer consumed in the PREVIOUS iteration).
// Edges sorted by (type, src): src-half gathers hit identical/adjacent L2 lines;
// tgt scatter stays randomly spread (avoids L2 per-address atomic serialization).

#define ROWB 80
#define BOFF 10240          // B hi offset (A = 128*80)
#define BSPL 20480          // B lo relative offset (256*80)
#define STAGE 51200
#define NSTAGE 4
#define SMEM_BYTES (1024 + NSTAGE * STAGE)

template<int MODE>
__global__ __launch_bounds__(512, 1)
void mma_gemm(const __half* __restrict__ Ah, int strideA, int K,
              const __half* __restrict__ Bh_, const __half* __restrict__ Bl_,
              int dout, float* __restrict__ Out,
              const int* __restrict__ src, const int* __restrict__ tgt,
              const float* __restrict__ bias, int Nrows,
              __half* __restrict__ OutH) {
    extern __shared__ char smem[];
    int tid = threadIdx.x;
    int wid = tid >> 5, lane = tid & 31;
    int row0 = blockIdx.x * 128;
    int col0 = blockIdx.z * 256;

    const __half *Bh, *Bl;
    int cnt = 0, offT = 0;
    if (MODE == 0) {
        int t = blockIdx.y;
        cnt = g_cnt[t];
        if (row0 >= cnt) return;
        offT = g_off[t];
        Bh = Bh_ + (size_t)t * dout * K;
        Bl = Bl_ + (size_t)t * dout * K;
    } else {
        if (row0 >= Nrows) return;
        Bh = Bh_; Bl = Bl_;
    }

    int* sSrc = (int*)smem;
    int* sTgt = (int*)(smem + 512);
    char* tiles = smem + 1024;
    uint32_t sb = smem_u32(tiles);

    if (MODE == 0 && tid < 128) {
        int r = row0 + tid;
        int sn = 0, tn = -1;
        if (r < cnt) { int e = g_typeEdges[offT + r]; sn = src[e]; tn = tgt[e]; }
        sSrc[tid] = sn; sTgt[tid] = tn;
    }
    __syncthreads();

    // ---- ldmatrix base addresses ----
    int warp_m = wid >> 3, warp_n = wid & 7;
    uint32_t aAddr[4], bAddr[2];
    {
        int r = (lane & 15), hi8 = (lane >> 4) & 1;
        #pragma unroll
        for (int mt = 0; mt < 4; mt++)
            aAddr[mt] = sb + (warp_m * 64 + mt * 16 + r) * ROWB + hi8 * 16;
        int nr = hi8 * 8 + (lane & 7), kq = (lane >> 3) & 1;
        #pragma unroll
        for (int g = 0; g < 2; g++)
            bAddr[g] = sb + BOFF + (warp_n * 32 + g * 16 + nr) * ROWB + kq * 16;
    }

    float acc[4][4][4];
    #pragma unroll
    for (int i = 0; i < 4; i++)
        #pragma unroll
        for (int j = 0; j < 4; j++)
            #pragma unroll
            for (int q = 0; q < 4; q++) acc[i][j][q] = 0.f;

    const int nch = K >> 5;   // K in {256,512,1024} -> nch in {8,16,32}

    // ---- async chunk loader ----
    auto load_chunk = [&](int c) {
        int kt = c * 32;
        uint32_t stg = sb + (c % NSTAGE) * STAGE;
        bool useSrc = true; int colb = kt;
        if (MODE == 0) { useSrc = kt < strideA; colb = useSrc ? kt : kt - strideA; }
        // A: 128 rows x 64B = 512 x 16B (single fp16)
        {
            int m = tid >> 2, u = tid & 3;
            const __half* srcp;
            if (MODE == 0) {
                int node = useSrc ? sSrc[m] : sTgt[m];
                if (node < 0) node = 0;
                srcp = Ah + (size_t)node * strideA + colb + u * 8;
            } else {
                int r = row0 + m; if (r >= Nrows) r = 0;
                srcp = Ah + (size_t)r * strideA + kt + u * 8;
            }
            cpa16(stg + m * ROWB + u * 16, srcp);
        }
        // B hi/lo: 2 x 256 rows x 64B = 2048 x 16B
        #pragma unroll
        for (int i = 0; i < 4; i++) {
            int slot = tid + i * 512;
            int split = slot >> 10, s2 = slot & 1023;
            int n = s2 >> 2, u = s2 & 3;
            const __half* bs = split ? Bl : Bh;
            cpa16(stg + BOFF + split * BSPL + n * ROWB + u * 16,
                  bs + (size_t)(col0 + n) * K + kt + u * 8);
        }
        asm volatile("cp.async.commit_group;" ::: "memory");
    };

    // prologue: stage 3 chunks (prefetch distance 3, 4 buffers)
    load_chunk(0);
    load_chunk(1);
    load_chunk(2);

    for (int c = 0; c < nch; c++) {
        asm volatile("cp.async.wait_group 2;" ::: "memory");   // chunk c complete
        __syncthreads();                                       // visibility + buffer reuse guard
        if (c + 3 < nch) load_chunk(c + 3);                    // buffer consumed last iter
        else asm volatile("cp.async.commit_group;" ::: "memory");  // keep group count stable

        uint32_t stoff = (c % NSTAGE) * STAGE;
        #pragma unroll
        for (int ks = 0; ks < 2; ks++) {
            uint32_t ko = stoff + ks * 32;
            uint32_t bhf[2][4], blf[2][4];
            ldm_x4(bAddr[0] + ko, bhf[0]);
            ldm_x4(bAddr[1] + ko, bhf[1]);
            ldm_x4(bAddr[0] + ko + BSPL, blf[0]);
            ldm_x4(bAddr[1] + ko + BSPL, blf[1]);
            #pragma unroll
            for (int mt = 0; mt < 4; mt++) {
                uint32_t ah[4];
                ldm_x4(aAddr[mt] + ko, ah);
                #pragma unroll
                for (int nt = 0; nt < 4; nt++) {
                    const uint32_t* ph = &bhf[nt >> 1][(nt & 1) * 2];
                    const uint32_t* pl = &blf[nt >> 1][(nt & 1) * 2];
                    mma16816(acc[mt][nt], ah, ph);
                    mma16816(acc[mt][nt], ah, pl);
                }
            }
        }
    }

    // ---- epilogue ----
    #pragma unroll
    for (int mt = 0; mt < 4; mt++) {
        int rl = warp_m * 64 + mt * 16 + (lane >> 2);
        int rh = rl + 8;
        if (MODE == 0) {
            int v1 = sTgt[rl], v2 = sTgt[rh];
            #pragma unroll
            for (int nt = 0; nt < 4; nt++) {
                int c = col0 + warp_n * 32 + nt * 8 + 2 * (lane & 3);
                if (v1 >= 0) red2(&Out[(size_t)v1 * dout + c], acc[mt][nt][0], acc[mt][nt][1]);
                if (v2 >= 0) red2(&Out[(size_t)v2 * dout + c], acc[mt][nt][2], acc[mt][nt][3]);
            }
        } else {
            int g1 = row0 + rl, g2 = row0 + rh;
            #pragma unroll
            for (int nt = 0; nt < 4; nt++) {
                int c = col0 + warp_n * 32 + nt * 8 + 2 * (lane & 3);
                float b0 = bias[c], b1 = bias[c + 1];
                if (g1 < Nrows) {
                    float y0 = tanhf(acc[mt][nt][0] + b0);
                    float y1 = tanhf(acc[mt][nt][1] + b1);
                    if (Out) {
                        Out[(size_t)g1 * dout + c]     = y0;
                        Out[(size_t)g1 * dout + c + 1] = y1;
                    }
                    if (OutH) *(uint32_t*)(OutH + (size_t)g1 * dout + c) = pk_h2(y0, y1);
                }
                if (g2 < Nrows) {
                    float y0 = tanhf(acc[mt][nt][2] + b0);
                    float y1 = tanhf(acc[mt][nt][3] + b1);
                    if (Out) {
                        Out[(size_t)g2 * dout + c]     = y0;
                        Out[(size_t)g2 * dout + c + 1] = y1;
                    }
                    if (OutH) *(uint32_t*)(OutH + (size_t)g2 * dout + c) = pk_h2(y0, y1);
                }
            }
        }
    }
}

// ---------------- host-side driver ----------------
static void run_gnn_layer(int din, int N, int E,
                          __half* Sh, __half* Mh,
                          const __half* Weh, const __half* Wel,
                          const float* ls, const float* lb,
                          const __half* Wdh, const __half* Wdl,
                          const float* bias, float* destF, float* Mbuf,
                          __half* destH,
                          const int* src, const int* tgt) {
    long long n4 = (long long)N * din / 4;
    clear_f4_kernel<<<4096, 256>>>((float4*)Mbuf, n4);
    dim3 egrid((E + 127) / 128, 4, din > 256 ? din / 256 : 1);
    mma_gemm<0><<<egrid, 512, SMEM_BYTES>>>(Sh, din, 2 * din, Weh, Wel, din, Mbuf,
                                            src, tgt, nullptr, 0, nullptr);
    gelu_ln_kernel<<<(N + 7) / 8, 256>>>((const float4*)Mbuf, (const float4*)ls,
                                         (const float4*)lb, (uint2*)Mh, din, N);
    dim3 dgrid((N + 127) / 128, 1, 1);
    mma_gemm<1><<<dgrid, 512, SMEM_BYTES>>>(Mh, din, din, Wdh, Wdl, 256, destF,
                                            nullptr, nullptr, bias, N, destH);
}

extern "C" void kernel_launch(void* const* d_in, const int* in_sizes, int n_in,
                              void* d_out, int out_size) {
    const int*   ids   = (const int*)d_in[0];
    const int*   te    = (const int*)d_in[1];
    const float* embed = (const float*)d_in[2];
    const float* WeI   = (const float*)d_in[3];
    const float* lsI   = (const float*)d_in[4];
    const float* lbI   = (const float*)d_in[5];
    const float* WdI   = (const float*)d_in[6];
    const float* bdI   = (const float*)d_in[7];
    const float* WeO   = (const float*)d_in[8];
    const float* lsO   = (const float*)d_in[9];
    const float* lbO   = (const float*)d_in[10];
    const float* WdO   = (const float*)d_in[11];
    const float* bdO   = (const float*)d_in[12];
    float* out = (float*)d_out;

    int N = in_sizes[0];
    int E = in_sizes[1] / 3;
    const int* etype = te;
    const int* src   = te + E;
    const int* tgt   = te + 2 * E;

    float *S0, *S1, *M;
    __half *Sh, *Mh;
    __half *WeIh, *WeIl, *WeOh, *WeOl, *WdIh, *WdIl, *WdOh, *WdOl;
    cudaGetSymbolAddress((void**)&S0, g_S0);
    cudaGetSymbolAddress((void**)&S1, g_S1);
    cudaGetSymbolAddress((void**)&M,  g_M);
    cudaGetSymbolAddress((void**)&Sh, g_Sh);
    cudaGetSymbolAddress((void**)&Mh, g_Mh);
    cudaGetSymbolAddress((void**)&WeIh, g_WeI_h);
    cudaGetSymbolAddress((void**)&WeIl, g_WeI_l);
    cudaGetSymbolAddress((void**)&WeOh, g_WeO_h);
    cudaGetSymbolAddress((void**)&WeOl, g_WeO_l);
    cudaGetSymbolAddress((void**)&WdIh, g_WdI_h);
    cudaGetSymbolAddress((void**)&WdIl, g_WdI_l);
    cudaGetSymbolAddress((void**)&WdOh, g_WdO_h);
    cudaGetSymbolAddress((void**)&WdOl, g_WdO_l);

    cudaFuncSetAttribute(mma_gemm<0>, cudaFuncAttributeMaxDynamicSharedMemorySize, SMEM_BYTES);
    cudaFuncSetAttribute(mma_gemm<1>, cudaFuncAttributeMaxDynamicSharedMemorySize, SMEM_BYTES);

    // --- preprocessing: counting sort of edges by (type, src) ---
    clear_counts_kernel<<<1, 32>>>();
    count_types_kernel<<<(E + 255) / 256, 256>>>(etype, E);
    offsets_kernel<<<1, 1>>>();
    clear_tpos_kernel<<<512, 256>>>();
    count_tv_kernel<<<(E + 255) / 256, 256>>>(etype, src, E);
    assign_start_kernel<<<512, 256>>>();
    scatter_sorted_kernel<<<(E + 255) / 256, 256>>>(etype, src, E);

    int nWeI = 6 * 4 * 256 * 512, nWeO = 2 * 4 * 512 * 1024;
    int nWdI = 6 * 256 * 256,     nWdO = 2 * 256 * 512;
    conv_f16_kernel<<<(nWeI + 255) / 256, 256>>>(WeI, WeIh, WeIl, nWeI);
    conv_f16_kernel<<<(nWeO + 255) / 256, 256>>>(WeO, WeOh, WeOl, nWeO);
    conv_f16_kernel<<<(nWdI + 255) / 256, 256>>>(WdI, WdIh, WdIl, nWdI);
    conv_f16_kernel<<<(nWdO + 255) / 256, 256>>>(WdO, WdOh, WdOl, nWdO);

    embed_kernel<<<(N * 64 + 255) / 256, 256>>>((const float4*)embed, ids, (float4*)S0,
                                                (uint2*)Sh, N);

    // Buffer dance (no SAVE copy): block-start fp32 lives in S0 for the whole block;
    // inner L1/L2 fp32 outputs are dead (only fp16 twin consumed) -> skipped;
    // inner L3 fp32 -> S1; concat(S0, S1) -> Sh(512); outer fp32 -> S0 (b=0) / out (b=1).
    for (int b = 0; b < 2; b++) {
        for (int i = 0; i < 3; i++) {
            int l = 3 * b + i;
            float* destF = (i == 2) ? S1 : nullptr;
            run_gnn_layer(256, N, E, Sh, Mh,
                          WeIh + (size_t)l * 4 * 256 * 512, WeIl + (size_t)l * 4 * 256 * 512,
                          lsI + (size_t)l * 256, lbI + (size_t)l * 256,
                          WdIh + (size_t)l * 256 * 256, WdIl + (size_t)l * 256 * 256,
                          bdI + (size_t)l * 256,
                          destF, M, Sh, src, tgt);
        }
        concat_f16_kernel<<<(N * 128 + 255) / 256, 256>>>((const float4*)S0,
                                                          (const float4*)S1, Sh, N);
        float* destF = (b == 1) ? out : S0;
        run_gnn_layer(512, N, E, Sh, Mh,
                      WeOh + (size_t)b * 4 * 512 * 1024, WeOl + (size_t)b * 4 * 512 * 1024,
                      lsO + (size_t)b * 512, lbO + (size_t)b * 512,
                      WdOh + (size_t)b * 256 * 512, WdOl + (size_t)b * 256 * 512,
                      bdO + (size_t)b * 256,
                      destF, M,
                      (b == 0) ? Sh : nullptr,
                      src, tgt);
    }
}

// round 15
// speedup vs baseline: 1.0600x; 1.0600x over previous
#include <cuda_runtime.h>
#include <cuda_fp16.h>
#include <math.h>
#include <stdint.h>

#define MAXN 100000
#define MAXE 320000

// ---------------- scratch (device globals; no allocs allowed) ----------------
__device__ __align__(16) float g_S0[(size_t)MAXN * 256];
__device__ __align__(16) float g_S1[(size_t)MAXN * 256];
__device__ __align__(16) float g_M [(size_t)MAXN * 512];

// fp16 state + message (single precision copy; A-side of GEMMs)
__device__ __align__(16) __half g_Sh[(size_t)MAXN * 512];
__device__ __align__(16) __half g_Mh[(size_t)MAXN * 512];

// fp16 hi/lo weight splits (natural [dout][K] layout == col-major B for mma.row.col)
__device__ __align__(16) __half g_WeI_h[6 * 4 * 256 * 512],  g_WeI_l[6 * 4 * 256 * 512];
__device__ __align__(16) __half g_WeO_h[2 * 4 * 512 * 1024], g_WeO_l[2 * 4 * 512 * 1024];
__device__ __align__(16) __half g_WdI_h[6 * 256 * 256],      g_WdI_l[6 * 256 * 256];
__device__ __align__(16) __half g_WdO_h[2 * 256 * 512],      g_WdO_l[2 * 256 * 512];

__device__ int g_typeEdges[MAXE];
__device__ int g_cnt[4], g_off[4], g_cur[4];

// ---------------- helpers ----------------
__device__ __forceinline__ uint32_t smem_u32(const void* p) {
    uint32_t a;
    asm("{ .reg .u64 t; cvta.to.shared.u64 t, %1; cvt.u32.u64 %0, t; }" : "=r"(a) : "l"(p));
    return a;
}

__device__ __forceinline__ void ldm_x4(uint32_t addr, uint32_t r[4]) {
    asm volatile("ldmatrix.sync.aligned.m8n8.x4.shared.b16 {%0,%1,%2,%3}, [%4];"
                 : "=r"(r[0]), "=r"(r[1]), "=r"(r[2]), "=r"(r[3]) : "r"(addr));
}

__device__ __forceinline__ void mma16816(float c[4], const uint32_t a[4], const uint32_t b[2]) {
    asm volatile(
        "mma.sync.aligned.m16n8k16.row.col.f32.f16.f16.f32 "
        "{%0,%1,%2,%3}, {%4,%5,%6,%7}, {%8,%9}, {%0,%1,%2,%3};"
        : "+f"(c[0]), "+f"(c[1]), "+f"(c[2]), "+f"(c[3])
        : "r"(a[0]), "r"(a[1]), "r"(a[2]), "r"(a[3]), "r"(b[0]), "r"(b[1]));
}

__device__ __forceinline__ void cpa16(uint32_t dst, const void* src) {
    asm volatile("cp.async.cg.shared.global [%0], [%1], 16;" :: "r"(dst), "l"(src) : "memory");
}

// vectorized f32 reduction (PTX ISA 8.1, sm_90+)
__device__ __forceinline__ void red2(float* addr, float a, float b) {
    asm volatile("red.global.add.v2.f32 [%0], {%1, %2};" :: "l"(addr), "f"(a), "f"(b) : "memory");
}

__device__ __forceinline__ uint32_t pk_h2(float a, float b) {
    __half2 t = __floats2half2_rn(a, b);
    return reinterpret_cast<uint32_t&>(t);
}

__device__ __forceinline__ float gelu_f(float x) {
    return 0.5f * x * (1.0f + erff(x * 0.70710678118654752f));
}

// ---------------- small utility kernels ----------------
__global__ void clear_f4_kernel(float4* p, long long n4) {
    long long i = (long long)blockIdx.x * blockDim.x + threadIdx.x;
    long long stride = (long long)gridDim.x * blockDim.x;
    float4 z = make_float4(0.f, 0.f, 0.f, 0.f);
    for (; i < n4; i += stride) p[i] = z;
}

__global__ void clear_counts_kernel() {
    int i = threadIdx.x;
    if (i < 4) { g_cnt[i] = 0; g_cur[i] = 0; }
}

// smem block-histogram: 4 global atomics per block instead of 1 per edge
__global__ void count_types_kernel(const int* __restrict__ etype, int E) {
    __shared__ int h[4];
    if (threadIdx.x < 4) h[threadIdx.x] = 0;
    __syncthreads();
    int e = blockIdx.x * blockDim.x + threadIdx.x;
    if (e < E) atomicAdd(&h[etype[e] - 1], 1);
    __syncthreads();
    if (threadIdx.x < 4 && h[threadIdx.x] > 0) atomicAdd(&g_cnt[threadIdx.x], h[threadIdx.x]);
}

__global__ void offsets_kernel() {
    if (threadIdx.x == 0) {
        g_off[0] = 0;
        g_off[1] = g_cnt[0];
        g_off[2] = g_cnt[0] + g_cnt[1];
        g_off[3] = g_cnt[0] + g_cnt[1] + g_cnt[2];
    }
}

// block-batched scatter: in-block rank via smem, one base atomic per (block,type)
__global__ void scatter_types_kernel(const int* __restrict__ etype, int E) {
    __shared__ int h[4], base[4];
    if (threadIdx.x < 4) h[threadIdx.x] = 0;
    __syncthreads();
    int e = blockIdx.x * blockDim.x + threadIdx.x;
    int t = -1, r = 0;
    if (e < E) { t = etype[e] - 1; r = atomicAdd(&h[t], 1); }
    __syncthreads();
    if (threadIdx.x < 4)
        base[threadIdx.x] = h[threadIdx.x] ? atomicAdd(&g_cur[threadIdx.x], h[threadIdx.x]) : 0;
    __syncthreads();
    if (t >= 0) g_typeEdges[g_off[t] + base[t] + r] = e;
}

// weights: fp32 -> fp16 hi + fp16 lo (residual)
__global__ void conv_f16_kernel(const float* __restrict__ w, __half* __restrict__ hi,
                                __half* __restrict__ lo, int n) {
    int i = blockIdx.x * blockDim.x + threadIdx.x;
    if (i >= n) return;
    float x = w[i];
    __half h = __float2half_rn(x);
    hi[i] = h;
    lo[i] = __float2half_rn(x - __half2float(h));
}

// embed + fp16 split fused: one pass over the gathered rows
__global__ void embed_kernel(const float4* __restrict__ tab, const int* __restrict__ ids,
                             float4* __restrict__ outS, uint2* __restrict__ Sh, int N) {
    int idx = blockIdx.x * blockDim.x + threadIdx.x;
    if (idx >= N * 64) return;
    int node = idx >> 6, c = idx & 63;
    int r = ids[node];
    float4 v = tab[(size_t)r * 64 + c];
    outS[(size_t)node * 64 + c] = v;
    Sh[(size_t)node * 64 + c] = make_uint2(pk_h2(v.x, v.y), pk_h2(v.z, v.w));
}

// concat [save(256) | x(256)] -> 512-wide fp16 state
__global__ void concat_f16_kernel(const float4* __restrict__ save, const float4* __restrict__ x,
                                  __half* __restrict__ Sh, int N) {
    int idx = blockIdx.x * blockDim.x + threadIdx.x;
    if (idx >= N * 128) return;
    int node = idx >> 7, c = idx & 127;
    float4 v = (c < 64) ? save[(size_t)node * 64 + c] : x[(size_t)node * 64 + (c - 64)];
    ((uint2*)(Sh + (size_t)node * 512))[c] = make_uint2(pk_h2(v.x, v.y), pk_h2(v.z, v.w));
}

// gelu + layernorm; float4-vectorized; emits fp16 directly
__global__ void gelu_ln_kernel(const float4* __restrict__ M, const float4* __restrict__ s4,
                               const float4* __restrict__ b4,
                               uint2* __restrict__ Mh, int dm, int N) {
    int warp = (blockIdx.x * blockDim.x + threadIdx.x) >> 5;
    int lane = threadIdx.x & 31;
    if (warp >= N) return;
    int n4 = dm >> 2;
    int per = n4 >> 5;
    const float4* row = M + (size_t)warp * n4;
    float4 v[4];
    float sum = 0.f;
    for (int i = 0; i < per; i++) {
        float4 x = row[i * 32 + lane];
        float4 g;
        g.x = gelu_f(x.x); g.y = gelu_f(x.y); g.z = gelu_f(x.z); g.w = gelu_f(x.w);
        v[i] = g;
        sum += g.x + g.y + g.z + g.w;
    }
    #pragma unroll
    for (int o = 16; o > 0; o >>= 1) sum += __shfl_xor_sync(0xFFFFFFFF, sum, o);
    float mu = sum / (float)dm;
    float vs = 0.f;
    for (int i = 0; i < per; i++) {
        float dx = v[i].x - mu, dy = v[i].y - mu, dz = v[i].z - mu, dw = v[i].w - mu;
        vs += dx * dx + dy * dy + dz * dz + dw * dw;
    }
    #pragma unroll
    for (int o = 16; o > 0; o >>= 1) vs += __shfl_xor_sync(0xFFFFFFFF, vs, o);
    float inv = rsqrtf(vs / (float)dm + 1e-5f);
    for (int i = 0; i < per; i++) {
        int c4 = i * 32 + lane;
        float4 sv = s4[c4], bv = b4[c4];
        float y0 = (v[i].x - mu) * inv * sv.x + bv.x;
        float y1 = (v[i].y - mu) * inv * sv.y + bv.y;
        float y2 = (v[i].z - mu) * inv * sv.z + bv.z;
        float y3 = (v[i].w - mu) * inv * sv.w + bv.w;
        Mh[(size_t)warp * n4 + c4] = make_uint2(pk_h2(y0, y1), pk_h2(y2, y3));
    }
}

// ---------------- mma.sync GEMM (MODE 0: edge gather+scatter, MODE 1: dense+tanh) ----------------
// fp16 2-term: C = A_f16 @ (Bh + Bl).  CTA tile 256(M) x 128(N) — M-major to HALVE
// B weight re-reads (B traffic ∝ rowTiles). K chunk 32.
// 512 threads = 16 warps (4x4), warp tile 64x32. 4-stage cp.async pipeline,
// prefetch distance 3 (load target buffer consumed in the PREVIOUS iteration).

#define ROWB 80
#define BOFF 20480          // B hi offset (A = 256*80)
#define BSPL 10240          // B lo relative offset (128*80)
#define STAGE 40960
#define NSTAGE 4
#define SMEM_BYTES (2048 + NSTAGE * STAGE)

template<int MODE>
__global__ __launch_bounds__(512, 1)
void mma_gemm(const __half* __restrict__ Ah, int strideA, int K,
              const __half* __restrict__ Bh_, const __half* __restrict__ Bl_,
              int dout, float* __restrict__ Out,
              const int* __restrict__ src, const int* __restrict__ tgt,
              const float* __restrict__ bias, int Nrows,
              __half* __restrict__ OutH) {
    extern __shared__ char smem[];
    int tid = threadIdx.x;
    int wid = tid >> 5, lane = tid & 31;
    int row0 = blockIdx.x * 256;
    int col0 = blockIdx.z * 128;

    const __half *Bh, *Bl;
    int cnt = 0, offT = 0;
    if (MODE == 0) {
        int t = blockIdx.y;
        cnt = g_cnt[t];
        if (row0 >= cnt) return;
        offT = g_off[t];
        Bh = Bh_ + (size_t)t * dout * K;
        Bl = Bl_ + (size_t)t * dout * K;
    } else {
        if (row0 >= Nrows) return;
        Bh = Bh_; Bl = Bl_;
    }

    int* sSrc = (int*)smem;            // 256 ints
    int* sTgt = (int*)(smem + 1024);   // 256 ints
    char* tiles = smem + 2048;
    uint32_t sb = smem_u32(tiles);

    if (MODE == 0 && tid < 256) {
        int r = row0 + tid;
        int sn = 0, tn = -1;
        if (r < cnt) { int e = g_typeEdges[offT + r]; sn = src[e]; tn = tgt[e]; }
        sSrc[tid] = sn; sTgt[tid] = tn;
    }
    __syncthreads();

    // ---- ldmatrix base addresses: 16 warps as 4(m) x 4(n) ----
    int warp_m = wid >> 2, warp_n = wid & 3;
    uint32_t aAddr[4], bAddr[2];
    {
        int r = (lane & 15), hi8 = (lane >> 4) & 1;
        #pragma unroll
        for (int mt = 0; mt < 4; mt++)
            aAddr[mt] = sb + (warp_m * 64 + mt * 16 + r) * ROWB + hi8 * 16;
        int nr = hi8 * 8 + (lane & 7), kq = (lane >> 3) & 1;
        #pragma unroll
        for (int g = 0; g < 2; g++)
            bAddr[g] = sb + BOFF + (warp_n * 32 + g * 16 + nr) * ROWB + kq * 16;
    }

    float acc[4][4][4];
    #pragma unroll
    for (int i = 0; i < 4; i++)
        #pragma unroll
        for (int j = 0; j < 4; j++)
            #pragma unroll
            for (int q = 0; q < 4; q++) acc[i][j][q] = 0.f;

    const int nch = K >> 5;   // K in {256,512,1024} -> nch in {8,16,32}

    // ---- async chunk loader ----
    auto load_chunk = [&](int c) {
        int kt = c * 32;
        uint32_t stg = sb + (c % NSTAGE) * STAGE;
        bool useSrc = true; int colb = kt;
        if (MODE == 0) { useSrc = kt < strideA; colb = useSrc ? kt : kt - strideA; }
        // A: 256 rows x 64B = 1024 x 16B (2 per thread)
        #pragma unroll
        for (int i = 0; i < 2; i++) {
            int slot = tid + i * 512;
            int m = slot >> 2, u = slot & 3;
            const __half* srcp;
            if (MODE == 0) {
                int node = useSrc ? sSrc[m] : sTgt[m];
                if (node < 0) node = 0;
                srcp = Ah + (size_t)node * strideA + colb + u * 8;
            } else {
                int r = row0 + m; if (r >= Nrows) r = 0;
                srcp = Ah + (size_t)r * strideA + kt + u * 8;
            }
            cpa16(stg + m * ROWB + u * 16, srcp);
        }
        // B hi/lo: 2 x 128 rows x 64B = 1024 x 16B (2 per thread)
        #pragma unroll
        for (int i = 0; i < 2; i++) {
            int slot = tid + i * 512;
            int split = slot >> 9, s2 = slot & 511;
            int n = s2 >> 2, u = s2 & 3;
            const __half* bs = split ? Bl : Bh;
            cpa16(stg + BOFF + split * BSPL + n * ROWB + u * 16,
                  bs + (size_t)(col0 + n) * K + kt + u * 8);
        }
        asm volatile("cp.async.commit_group;" ::: "memory");
    };

    // prologue: stage 3 chunks (prefetch distance 3, 4 buffers)
    load_chunk(0);
    load_chunk(1);
    load_chunk(2);

    for (int c = 0; c < nch; c++) {
        asm volatile("cp.async.wait_group 2;" ::: "memory");   // chunk c complete
        __syncthreads();                                       // visibility + buffer reuse guard
        if (c + 3 < nch) load_chunk(c + 3);                    // buffer consumed last iter
        else asm volatile("cp.async.commit_group;" ::: "memory");  // keep group count stable

        uint32_t stoff = (c % NSTAGE) * STAGE;
        #pragma unroll
        for (int ks = 0; ks < 2; ks++) {
            uint32_t ko = stoff + ks * 32;
            uint32_t bhf[2][4], blf[2][4];
            ldm_x4(bAddr[0] + ko, bhf[0]);
            ldm_x4(bAddr[1] + ko, bhf[1]);
            ldm_x4(bAddr[0] + ko + BSPL, blf[0]);
            ldm_x4(bAddr[1] + ko + BSPL, blf[1]);
            #pragma unroll
            for (int mt = 0; mt < 4; mt++) {
                uint32_t ah[4];
                ldm_x4(aAddr[mt] + ko, ah);
                #pragma unroll
                for (int nt = 0; nt < 4; nt++) {
                    const uint32_t* ph = &bhf[nt >> 1][(nt & 1) * 2];
                    const uint32_t* pl = &blf[nt >> 1][(nt & 1) * 2];
                    mma16816(acc[mt][nt], ah, ph);
                    mma16816(acc[mt][nt], ah, pl);
                }
            }
        }
    }

    // ---- epilogue ----
    #pragma unroll
    for (int mt = 0; mt < 4; mt++) {
        int rl = warp_m * 64 + mt * 16 + (lane >> 2);
        int rh = rl + 8;
        if (MODE == 0) {
            int v1 = sTgt[rl], v2 = sTgt[rh];
            #pragma unroll
            for (int nt = 0; nt < 4; nt++) {
                int c = col0 + warp_n * 32 + nt * 8 + 2 * (lane & 3);
                if (v1 >= 0) red2(&Out[(size_t)v1 * dout + c], acc[mt][nt][0], acc[mt][nt][1]);
                if (v2 >= 0) red2(&Out[(size_t)v2 * dout + c], acc[mt][nt][2], acc[mt][nt][3]);
            }
        } else {
            int g1 = row0 + rl, g2 = row0 + rh;
            #pragma unroll
            for (int nt = 0; nt < 4; nt++) {
                int c = col0 + warp_n * 32 + nt * 8 + 2 * (lane & 3);
                float b0 = bias[c], b1 = bias[c + 1];
                if (g1 < Nrows) {
                    float y0 = tanhf(acc[mt][nt][0] + b0);
                    float y1 = tanhf(acc[mt][nt][1] + b1);
                    if (Out) {
                        Out[(size_t)g1 * dout + c]     = y0;
                        Out[(size_t)g1 * dout + c + 1] = y1;
                    }
                    if (OutH) *(uint32_t*)(OutH + (size_t)g1 * dout + c) = pk_h2(y0, y1);
                }
                if (g2 < Nrows) {
                    float y0 = tanhf(acc[mt][nt][2] + b0);
                    float y1 = tanhf(acc[mt][nt][3] + b1);
                    if (Out) {
                        Out[(size_t)g2 * dout + c]     = y0;
                        Out[(size_t)g2 * dout + c + 1] = y1;
                    }
                    if (OutH) *(uint32_t*)(OutH + (size_t)g2 * dout + c) = pk_h2(y0, y1);
                }
            }
        }
    }
}

// ---------------- host-side driver ----------------
static void run_gnn_layer(int din, int N, int E,
                          __half* Sh, __half* Mh,
                          const __half* Weh, const __half* Wel,
                          const float* ls, const float* lb,
                          const __half* Wdh, const __half* Wdl,
                          const float* bias, float* destF, float* Mbuf,
                          __half* destH,
                          const int* src, const int* tgt) {
    long long n4 = (long long)N * din / 4;
    clear_f4_kernel<<<4096, 256>>>((float4*)Mbuf, n4);
    dim3 egrid((E + 255) / 256, 4, din / 128);           // N-tile 128: 2 or 4 col tiles
    mma_gemm<0><<<egrid, 512, SMEM_BYTES>>>(Sh, din, 2 * din, Weh, Wel, din, Mbuf,
                                            src, tgt, nullptr, 0, nullptr);
    gelu_ln_kernel<<<(N + 7) / 8, 256>>>((const float4*)Mbuf, (const float4*)ls,
                                         (const float4*)lb, (uint2*)Mh, din, N);
    dim3 dgrid((N + 255) / 256, 1, 2);                   // dout=256 -> 2 col tiles
    mma_gemm<1><<<dgrid, 512, SMEM_BYTES>>>(Mh, din, din, Wdh, Wdl, 256, destF,
                                            nullptr, nullptr, bias, N, destH);
}

extern "C" void kernel_launch(void* const* d_in, const int* in_sizes, int n_in,
                              void* d_out, int out_size) {
    const int*   ids   = (const int*)d_in[0];
    const int*   te    = (const int*)d_in[1];
    const float* embed = (const float*)d_in[2];
    const float* WeI   = (const float*)d_in[3];
    const float* lsI   = (const float*)d_in[4];
    const float* lbI   = (const float*)d_in[5];
    const float* WdI   = (const float*)d_in[6];
    const float* bdI   = (const float*)d_in[7];
    const float* WeO   = (const float*)d_in[8];
    const float* lsO   = (const float*)d_in[9];
    const float* lbO   = (const float*)d_in[10];
    const float* WdO   = (const float*)d_in[11];
    const float* bdO   = (const float*)d_in[12];
    float* out = (float*)d_out;

    int N = in_sizes[0];
    int E = in_sizes[1] / 3;
    const int* etype = te;
    const int* src   = te + E;
    const int* tgt   = te + 2 * E;

    float *S0, *S1, *M;
    __half *Sh, *Mh;
    __half *WeIh, *WeIl, *WeOh, *WeOl, *WdIh, *WdIl, *WdOh, *WdOl;
    cudaGetSymbolAddress((void**)&S0, g_S0);
    cudaGetSymbolAddress((void**)&S1, g_S1);
    cudaGetSymbolAddress((void**)&M,  g_M);
    cudaGetSymbolAddress((void**)&Sh, g_Sh);
    cudaGetSymbolAddress((void**)&Mh, g_Mh);
    cudaGetSymbolAddress((void**)&WeIh, g_WeI_h);
    cudaGetSymbolAddress((void**)&WeIl, g_WeI_l);
    cudaGetSymbolAddress((void**)&WeOh, g_WeO_h);
    cudaGetSymbolAddress((void**)&WeOl, g_WeO_l);
    cudaGetSymbolAddress((void**)&WdIh, g_WdI_h);
    cudaGetSymbolAddress((void**)&WdIl, g_WdI_l);
    cudaGetSymbolAddress((void**)&WdOh, g_WdO_h);
    cudaGetSymbolAddress((void**)&WdOl, g_WdO_l);

    cudaFuncSetAttribute(mma_gemm<0>, cudaFuncAttributeMaxDynamicSharedMemorySize, SMEM_BYTES);
    cudaFuncSetAttribute(mma_gemm<1>, cudaFuncAttributeMaxDynamicSharedMemorySize, SMEM_BYTES);

    // --- preprocessing (R10 form: unsorted, block-batched) ---
    clear_counts_kernel<<<1, 32>>>();
    count_types_kernel<<<(E + 255) / 256, 256>>>(etype, E);
    offsets_kernel<<<1, 1>>>();
    scatter_types_kernel<<<(E + 255) / 256, 256>>>(etype, E);

    int nWeI = 6 * 4 * 256 * 512, nWeO = 2 * 4 * 512 * 1024;
    int nWdI = 6 * 256 * 256,     nWdO = 2 * 256 * 512;
    conv_f16_kernel<<<(nWeI + 255) / 256, 256>>>(WeI, WeIh, WeIl, nWeI);
    conv_f16_kernel<<<(nWeO + 255) / 256, 256>>>(WeO, WeOh, WeOl, nWeO);
    conv_f16_kernel<<<(nWdI + 255) / 256, 256>>>(WdI, WdIh, WdIl, nWdI);
    conv_f16_kernel<<<(nWdO + 255) / 256, 256>>>(WdO, WdOh, WdOl, nWdO);

    embed_kernel<<<(N * 64 + 255) / 256, 256>>>((const float4*)embed, ids, (float4*)S0,
                                                (uint2*)Sh, N);

    // Buffer dance (no SAVE copy): block-start fp32 lives in S0 for the whole block;
    // inner L1/L2 fp32 outputs are dead (only fp16 twin consumed) -> skipped;
    // inner L3 fp32 -> S1; concat(S0, S1) -> Sh(512); outer fp32 -> S0 (b=0) / out (b=1).
    for (int b = 0; b < 2; b++) {
        for (int i = 0; i < 3; i++) {
            int l = 3 * b + i;
            float* destF = (i == 2) ? S1 : nullptr;
            run_gnn_layer(256, N, E, Sh, Mh,
                          WeIh + (size_t)l * 4 * 256 * 512, WeIl + (size_t)l * 4 * 256 * 512,
                          lsI + (size_t)l * 256, lbI + (size_t)l * 256,
                          WdIh + (size_t)l * 256 * 256, WdIl + (size_t)l * 256 * 256,
                          bdI + (size_t)l * 256,
                          destF, M, Sh, src, tgt);
        }
        concat_f16_kernel<<<(N * 128 + 255) / 256, 256>>>((const float4*)S0,
                                                          (const float4*)S1, Sh, N);
        float* destF = (b == 1) ? out : S0;
        run_gnn_layer(512, N, E, Sh, Mh,
                      WeOh + (size_t)b * 4 * 512 * 1024, WeOl + (size_t)b * 4 * 512 * 1024,
                      lsO + (size_t)b * 512, lbO + (size_t)b * 512,
                      WdOh + (size_t)b * 256 * 512, WdOl + (size_t)b * 256 * 512,
                      bdO + (size_t)b * 256,
                      destF, M,
                      (b == 0) ? Sh : nullptr,
                      src, tgt);
    }
}

// round 16
// speedup vs baseline: 1.1020x; 1.0396x over previous
#include <cuda_runtime.h>
#include <cuda_fp16.h>
#include <math.h>
#include <stdint.h>

#define MAXN 100000
#define MAXE 320000

// ---------------- scratch (device globals; no allocs allowed) ----------------
__device__ __align__(16) float g_S0[(size_t)MAXN * 256];
__device__ __align__(16) float g_S1[(size_t)MAXN * 256];
__device__ __align__(16) float g_M [(size_t)MAXN * 512];

// fp16 state + message (single precision copy; A-side of GEMMs)
__device__ __align__(16) __half g_Sh[(size_t)MAXN * 512];
__device__ __align__(16) __half g_Mh[(size_t)MAXN * 512];

// fp16 hi/lo weight splits (natural [dout][K] layout == col-major B for mma.row.col)
__device__ __align__(16) __half g_WeI_h[6 * 4 * 256 * 512],  g_WeI_l[6 * 4 * 256 * 512];
__device__ __align__(16) __half g_WeO_h[2 * 4 * 512 * 1024], g_WeO_l[2 * 4 * 512 * 1024];
__device__ __align__(16) __half g_WdI_h[6 * 256 * 256],      g_WdI_l[6 * 256 * 256];
__device__ __align__(16) __half g_WdO_h[2 * 256 * 512],      g_WdO_l[2 * 256 * 512];

__device__ int g_typeEdges[MAXE];
__device__ int g_cnt[4], g_off[4], g_cur[4];

// ---------------- helpers ----------------
__device__ __forceinline__ uint32_t smem_u32(const void* p) {
    uint32_t a;
    asm("{ .reg .u64 t; cvta.to.shared.u64 t, %1; cvt.u32.u64 %0, t; }" : "=r"(a) : "l"(p));
    return a;
}

__device__ __forceinline__ void ldm_x4(uint32_t addr, uint32_t r[4]) {
    asm volatile("ldmatrix.sync.aligned.m8n8.x4.shared.b16 {%0,%1,%2,%3}, [%4];"
                 : "=r"(r[0]), "=r"(r[1]), "=r"(r[2]), "=r"(r[3]) : "r"(addr));
}

__device__ __forceinline__ void mma16816(float c[4], const uint32_t a[4], const uint32_t b[2]) {
    asm volatile(
        "mma.sync.aligned.m16n8k16.row.col.f32.f16.f16.f32 "
        "{%0,%1,%2,%3}, {%4,%5,%6,%7}, {%8,%9}, {%0,%1,%2,%3};"
        : "+f"(c[0]), "+f"(c[1]), "+f"(c[2]), "+f"(c[3])
        : "r"(a[0]), "r"(a[1]), "r"(a[2]), "r"(a[3]), "r"(b[0]), "r"(b[1]));
}

__device__ __forceinline__ void cpa16(uint32_t dst, const void* src) {
    asm volatile("cp.async.cg.shared.global [%0], [%1], 16;" :: "r"(dst), "l"(src) : "memory");
}

// vectorized f32 reduction (PTX ISA 8.1, sm_90+)
__device__ __forceinline__ void red2(float* addr, float a, float b) {
    asm volatile("red.global.add.v2.f32 [%0], {%1, %2};" :: "l"(addr), "f"(a), "f"(b) : "memory");
}

__device__ __forceinline__ uint32_t pk_h2(float a, float b) {
    __half2 t = __floats2half2_rn(a, b);
    return reinterpret_cast<uint32_t&>(t);
}

__device__ __forceinline__ float gelu_f(float x) {
    return 0.5f * x * (1.0f + erff(x * 0.70710678118654752f));
}

// ---------------- small utility kernels ----------------
__global__ void clear_f4_kernel(float4* p, long long n4) {
    long long i = (long long)blockIdx.x * blockDim.x + threadIdx.x;
    long long stride = (long long)gridDim.x * blockDim.x;
    float4 z = make_float4(0.f, 0.f, 0.f, 0.f);
    for (; i < n4; i += stride) p[i] = z;
}

__global__ void clear_counts_kernel() {
    int i = threadIdx.x;
    if (i < 4) { g_cnt[i] = 0; g_cur[i] = 0; }
}

// smem block-histogram: 4 global atomics per block instead of 1 per edge
__global__ void count_types_kernel(const int* __restrict__ etype, int E) {
    __shared__ int h[4];
    if (threadIdx.x < 4) h[threadIdx.x] = 0;
    __syncthreads();
    int e = blockIdx.x * blockDim.x + threadIdx.x;
    if (e < E) atomicAdd(&h[etype[e] - 1], 1);
    __syncthreads();
    if (threadIdx.x < 4 && h[threadIdx.x] > 0) atomicAdd(&g_cnt[threadIdx.x], h[threadIdx.x]);
}

__global__ void offsets_kernel() {
    if (threadIdx.x == 0) {
        g_off[0] = 0;
        g_off[1] = g_cnt[0];
        g_off[2] = g_cnt[0] + g_cnt[1];
        g_off[3] = g_cnt[0] + g_cnt[1] + g_cnt[2];
    }
}

// block-batched scatter: in-block rank via smem, one base atomic per (block,type)
__global__ void scatter_types_kernel(const int* __restrict__ etype, int E) {
    __shared__ int h[4], base[4];
    if (threadIdx.x < 4) h[threadIdx.x] = 0;
    __syncthreads();
    int e = blockIdx.x * blockDim.x + threadIdx.x;
    int t = -1, r = 0;
    if (e < E) { t = etype[e] - 1; r = atomicAdd(&h[t], 1); }
    __syncthreads();
    if (threadIdx.x < 4)
        base[threadIdx.x] = h[threadIdx.x] ? atomicAdd(&g_cur[threadIdx.x], h[threadIdx.x]) : 0;
    __syncthreads();
    if (t >= 0) g_typeEdges[g_off[t] + base[t] + r] = e;
}

// weights: fp32 -> fp16 hi + fp16 lo (residual)
__global__ void conv_f16_kernel(const float* __restrict__ w, __half* __restrict__ hi,
                                __half* __restrict__ lo, int n) {
    int i = blockIdx.x * blockDim.x + threadIdx.x;
    if (i >= n) return;
    float x = w[i];
    __half h = __float2half_rn(x);
    hi[i] = h;
    lo[i] = __float2half_rn(x - __half2float(h));
}

// embed + fp16 split fused: one pass over the gathered rows
__global__ void embed_kernel(const float4* __restrict__ tab, const int* __restrict__ ids,
                             float4* __restrict__ outS, uint2* __restrict__ Sh, int N) {
    int idx = blockIdx.x * blockDim.x + threadIdx.x;
    if (idx >= N * 64) return;
    int node = idx >> 6, c = idx & 63;
    int r = ids[node];
    float4 v = tab[(size_t)r * 64 + c];
    outS[(size_t)node * 64 + c] = v;
    Sh[(size_t)node * 64 + c] = make_uint2(pk_h2(v.x, v.y), pk_h2(v.z, v.w));
}

// concat [save(256) | x(256)] -> 512-wide fp16 state
__global__ void concat_f16_kernel(const float4* __restrict__ save, const float4* __restrict__ x,
                                  __half* __restrict__ Sh, int N) {
    int idx = blockIdx.x * blockDim.x + threadIdx.x;
    if (idx >= N * 128) return;
    int node = idx >> 7, c = idx & 127;
    float4 v = (c < 64) ? save[(size_t)node * 64 + c] : x[(size_t)node * 64 + (c - 64)];
    ((uint2*)(Sh + (size_t)node * 512))[c] = make_uint2(pk_h2(v.x, v.y), pk_h2(v.z, v.w));
}

// gelu + layernorm; float4-vectorized; emits fp16 directly
__global__ void gelu_ln_kernel(const float4* __restrict__ M, const float4* __restrict__ s4,
                               const float4* __restrict__ b4,
                               uint2* __restrict__ Mh, int dm, int N) {
    int warp = (blockIdx.x * blockDim.x + threadIdx.x) >> 5;
    int lane = threadIdx.x & 31;
    if (warp >= N) return;
    int n4 = dm >> 2;
    int per = n4 >> 5;
    const float4* row = M + (size_t)warp * n4;
    float4 v[4];
    float sum = 0.f;
    for (int i = 0; i < per; i++) {
        float4 x = row[i * 32 + lane];
        float4 g;
        g.x = gelu_f(x.x); g.y = gelu_f(x.y); g.z = gelu_f(x.z); g.w = gelu_f(x.w);
        v[i] = g;
        sum += g.x + g.y + g.z + g.w;
    }
    #pragma unroll
    for (int o = 16; o > 0; o >>= 1) sum += __shfl_xor_sync(0xFFFFFFFF, sum, o);
    float mu = sum / (float)dm;
    float vs = 0.f;
    for (int i = 0; i < per; i++) {
        float dx = v[i].x - mu, dy = v[i].y - mu, dz = v[i].z - mu, dw = v[i].w - mu;
        vs += dx * dx + dy * dy + dz * dz + dw * dw;
    }
    #pragma unroll
    for (int o = 16; o > 0; o >>= 1) vs += __shfl_xor_sync(0xFFFFFFFF, vs, o);
    float inv = rsqrtf(vs / (float)dm + 1e-5f);
    for (int i = 0; i < per; i++) {
        int c4 = i * 32 + lane;
        float4 sv = s4[c4], bv = b4[c4];
        float y0 = (v[i].x - mu) * inv * sv.x + bv.x;
        float y1 = (v[i].y - mu) * inv * sv.y + bv.y;
        float y2 = (v[i].z - mu) * inv * sv.z + bv.z;
        float y3 = (v[i].w - mu) * inv * sv.w + bv.w;
        Mh[(size_t)warp * n4 + c4] = make_uint2(pk_h2(y0, y1), pk_h2(y2, y3));
    }
}

// ---------------- mma.sync GEMM (MODE 0: edge gather+scatter, MODE 1: dense+tanh) ----------------
// fp16 2-term: C = A_f16 @ (Bh + Bl).  CTA tile 256(M) x 128(N), K chunk 64 (128B rows).
// 512 threads = 16 warps (4x4), warp tile 64x32. 3-stage cp.async pipeline,
// prefetch distance 2 (load target buffer consumed in the PREVIOUS iteration).

#define ROWB 144            // 128B data + 16B pad (conflict-free: 4r mod 32 distinct)
#define BOFF 36864          // B hi offset (A = 256*144)
#define BSPL 18432          // B lo relative offset (128*144)
#define STAGE 73728
#define NSTAGE 3
#define SMEM_BYTES (2048 + NSTAGE * STAGE)

template<int MODE>
__global__ __launch_bounds__(512, 1)
void mma_gemm(const __half* __restrict__ Ah, int strideA, int K,
              const __half* __restrict__ Bh_, const __half* __restrict__ Bl_,
              int dout, float* __restrict__ Out,
              const int* __restrict__ src, const int* __restrict__ tgt,
              const float* __restrict__ bias, int Nrows,
              __half* __restrict__ OutH) {
    extern __shared__ char smem[];
    int tid = threadIdx.x;
    int wid = tid >> 5, lane = tid & 31;
    int row0 = blockIdx.x * 256;
    int col0 = blockIdx.z * 128;

    const __half *Bh, *Bl;
    int cnt = 0, offT = 0;
    if (MODE == 0) {
        int t = blockIdx.y;
        cnt = g_cnt[t];
        if (row0 >= cnt) return;
        offT = g_off[t];
        Bh = Bh_ + (size_t)t * dout * K;
        Bl = Bl_ + (size_t)t * dout * K;
    } else {
        if (row0 >= Nrows) return;
        Bh = Bh_; Bl = Bl_;
    }

    int* sSrc = (int*)smem;            // 256 ints
    int* sTgt = (int*)(smem + 1024);   // 256 ints
    char* tiles = smem + 2048;
    uint32_t sb = smem_u32(tiles);

    if (MODE == 0 && tid < 256) {
        int r = row0 + tid;
        int sn = 0, tn = -1;
        if (r < cnt) { int e = g_typeEdges[offT + r]; sn = src[e]; tn = tgt[e]; }
        sSrc[tid] = sn; sTgt[tid] = tn;
    }
    __syncthreads();

    // ---- ldmatrix base addresses: 16 warps as 4(m) x 4(n) ----
    int warp_m = wid >> 2, warp_n = wid & 3;
    uint32_t aAddr[4], bAddr[2];
    {
        int r = (lane & 15), hi8 = (lane >> 4) & 1;
        #pragma unroll
        for (int mt = 0; mt < 4; mt++)
            aAddr[mt] = sb + (warp_m * 64 + mt * 16 + r) * ROWB + hi8 * 16;
        int nr = hi8 * 8 + (lane & 7), kq = (lane >> 3) & 1;
        #pragma unroll
        for (int g = 0; g < 2; g++)
            bAddr[g] = sb + BOFF + (warp_n * 32 + g * 16 + nr) * ROWB + kq * 16;
    }

    float acc[4][4][4];
    #pragma unroll
    for (int i = 0; i < 4; i++)
        #pragma unroll
        for (int j = 0; j < 4; j++)
            #pragma unroll
            for (int q = 0; q < 4; q++) acc[i][j][q] = 0.f;

    const int nch = K >> 6;   // K in {256,512,1024} -> nch in {4,8,16}

    // ---- async chunk loader: 64 fp16 (128B) per row per chunk ----
    auto load_chunk = [&](int c) {
        int kt = c * 64;
        uint32_t stg = sb + (c % NSTAGE) * STAGE;
        bool useSrc = true; int colb = kt;
        if (MODE == 0) { useSrc = kt < strideA; colb = useSrc ? kt : kt - strideA; }
        // A: 256 rows x 128B = 2048 x 16B (4 per thread)
        #pragma unroll
        for (int i = 0; i < 4; i++) {
            int slot = tid + i * 512;
            int m = slot >> 3, u = slot & 7;
            const __half* srcp;
            if (MODE == 0) {
                int node = useSrc ? sSrc[m] : sTgt[m];
                if (node < 0) node = 0;
                srcp = Ah + (size_t)node * strideA + colb + u * 8;
            } else {
                int r = row0 + m; if (r >= Nrows) r = 0;
                srcp = Ah + (size_t)r * strideA + kt + u * 8;
            }
            cpa16(stg + m * ROWB + u * 16, srcp);
        }
        // B hi/lo: 2 x 128 rows x 128B = 2048 x 16B (4 per thread)
        #pragma unroll
        for (int i = 0; i < 4; i++) {
            int slot = tid + i * 512;
            int split = slot >> 10, s2 = slot & 1023;
            int n = s2 >> 3, u = s2 & 7;
            const __half* bs = split ? Bl : Bh;
            cpa16(stg + BOFF + split * BSPL + n * ROWB + u * 16,
                  bs + (size_t)(col0 + n) * K + kt + u * 8);
        }
        asm volatile("cp.async.commit_group;" ::: "memory");
    };

    // prologue: stage 2 chunks (prefetch distance 2, 3 buffers)
    load_chunk(0);
    load_chunk(1);

    for (int c = 0; c < nch; c++) {
        asm volatile("cp.async.wait_group 1;" ::: "memory");   // chunk c complete
        __syncthreads();                                       // visibility + buffer reuse guard
        if (c + 2 < nch) load_chunk(c + 2);                    // buffer (c+2)%3 = (c-1)%3: consumed last iter
        else asm volatile("cp.async.commit_group;" ::: "memory");  // keep group count stable

        uint32_t stoff = (c % NSTAGE) * STAGE;
        #pragma unroll
        for (int ks = 0; ks < 4; ks++) {
            uint32_t ko = stoff + ks * 32;
            uint32_t bhf[2][4], blf[2][4];
            ldm_x4(bAddr[0] + ko, bhf[0]);
            ldm_x4(bAddr[1] + ko, bhf[1]);
            ldm_x4(bAddr[0] + ko + BSPL, blf[0]);
            ldm_x4(bAddr[1] + ko + BSPL, blf[1]);
            #pragma unroll
            for (int mt = 0; mt < 4; mt++) {
                uint32_t ah[4];
                ldm_x4(aAddr[mt] + ko, ah);
                #pragma unroll
                for (int nt = 0; nt < 4; nt++) {
                    const uint32_t* ph = &bhf[nt >> 1][(nt & 1) * 2];
                    const uint32_t* pl = &blf[nt >> 1][(nt & 1) * 2];
                    mma16816(acc[mt][nt], ah, ph);
                    mma16816(acc[mt][nt], ah, pl);
                }
            }
        }
    }

    // ---- epilogue ----
    #pragma unroll
    for (int mt = 0; mt < 4; mt++) {
        int rl = warp_m * 64 + mt * 16 + (lane >> 2);
        int rh = rl + 8;
        if (MODE == 0) {
            int v1 = sTgt[rl], v2 = sTgt[rh];
            #pragma unroll
            for (int nt = 0; nt < 4; nt++) {
                int c = col0 + warp_n * 32 + nt * 8 + 2 * (lane & 3);
                if (v1 >= 0) red2(&Out[(size_t)v1 * dout + c], acc[mt][nt][0], acc[mt][nt][1]);
                if (v2 >= 0) red2(&Out[(size_t)v2 * dout + c], acc[mt][nt][2], acc[mt][nt][3]);
            }
        } else {
            int g1 = row0 + rl, g2 = row0 + rh;
            #pragma unroll
            for (int nt = 0; nt < 4; nt++) {
                int c = col0 + warp_n * 32 + nt * 8 + 2 * (lane & 3);
                float b0 = bias[c], b1 = bias[c + 1];
                if (g1 < Nrows) {
                    float y0 = tanhf(acc[mt][nt][0] + b0);
                    float y1 = tanhf(acc[mt][nt][1] + b1);
                    if (Out) {
                        Out[(size_t)g1 * dout + c]     = y0;
                        Out[(size_t)g1 * dout + c + 1] = y1;
                    }
                    if (OutH) *(uint32_t*)(OutH + (size_t)g1 * dout + c) = pk_h2(y0, y1);
                }
                if (g2 < Nrows) {
                    float y0 = tanhf(acc[mt][nt][2] + b0);
                    float y1 = tanhf(acc[mt][nt][3] + b1);
                    if (Out) {
                        Out[(size_t)g2 * dout + c]     = y0;
                        Out[(size_t)g2 * dout + c + 1] = y1;
                    }
                    if (OutH) *(uint32_t*)(OutH + (size_t)g2 * dout + c) = pk_h2(y0, y1);
                }
            }
        }
    }
}

// ---------------- host-side driver ----------------
static void run_gnn_layer(int din, int N, int E,
                          __half* Sh, __half* Mh,
                          const __half* Weh, const __half* Wel,
                          const float* ls, const float* lb,
                          const __half* Wdh, const __half* Wdl,
                          const float* bias, float* destF, float* Mbuf,
                          __half* destH,
                          const int* src, const int* tgt) {
    long long n4 = (long long)N * din / 4;
    clear_f4_kernel<<<4096, 256>>>((float4*)Mbuf, n4);
    dim3 egrid((E + 255) / 256, 4, din / 128);
    mma_gemm<0><<<egrid, 512, SMEM_BYTES>>>(Sh, din, 2 * din, Weh, Wel, din, Mbuf,
                                            src, tgt, nullptr, 0, nullptr);
    gelu_ln_kernel<<<(N + 7) / 8, 256>>>((const float4*)Mbuf, (const float4*)ls,
                                         (const float4*)lb, (uint2*)Mh, din, N);
    dim3 dgrid((N + 255) / 256, 1, 2);
    mma_gemm<1><<<dgrid, 512, SMEM_BYTES>>>(Mh, din, din, Wdh, Wdl, 256, destF,
                                            nullptr, nullptr, bias, N, destH);
}

extern "C" void kernel_launch(void* const* d_in, const int* in_sizes, int n_in,
                              void* d_out, int out_size) {
    const int*   ids   = (const int*)d_in[0];
    const int*   te    = (const int*)d_in[1];
    const float* embed = (const float*)d_in[2];
    const float* WeI   = (const float*)d_in[3];
    const float* lsI   = (const float*)d_in[4];
    const float* lbI   = (const float*)d_in[5];
    const float* WdI   = (const float*)d_in[6];
    const float* bdI   = (const float*)d_in[7];
    const float* WeO   = (const float*)d_in[8];
    const float* lsO   = (const float*)d_in[9];
    const float* lbO   = (const float*)d_in[10];
    const float* WdO   = (const float*)d_in[11];
    const float* bdO   = (const float*)d_in[12];
    float* out = (float*)d_out;

    int N = in_sizes[0];
    int E = in_sizes[1] / 3;
    const int* etype = te;
    const int* src   = te + E;
    const int* tgt   = te + 2 * E;

    float *S0, *S1, *M;
    __half *Sh, *Mh;
    __half *WeIh, *WeIl, *WeOh, *WeOl, *WdIh, *WdIl, *WdOh, *WdOl;
    cudaGetSymbolAddress((void**)&S0, g_S0);
    cudaGetSymbolAddress((void**)&S1, g_S1);
    cudaGetSymbolAddress((void**)&M,  g_M);
    cudaGetSymbolAddress((void**)&Sh, g_Sh);
    cudaGetSymbolAddress((void**)&Mh, g_Mh);
    cudaGetSymbolAddress((void**)&WeIh, g_WeI_h);
    cudaGetSymbolAddress((void**)&WeIl, g_WeI_l);
    cudaGetSymbolAddress((void**)&WeOh, g_WeO_h);
    cudaGetSymbolAddress((void**)&WeOl, g_WeO_l);
    cudaGetSymbolAddress((void**)&WdIh, g_WdI_h);
    cudaGetSymbolAddress((void**)&WdIl, g_WdI_l);
    cudaGetSymbolAddress((void**)&WdOh, g_WdO_h);
    cudaGetSymbolAddress((void**)&WdOl, g_WdO_l);

    cudaFuncSetAttribute(mma_gemm<0>, cudaFuncAttributeMaxDynamicSharedMemorySize, SMEM_BYTES);
    cudaFuncSetAttribute(mma_gemm<1>, cudaFuncAttributeMaxDynamicSharedMemorySize, SMEM_BYTES);

    // --- preprocessing (unsorted, block-batched) ---
    clear_counts_kernel<<<1, 32>>>();
    count_types_kernel<<<(E + 255) / 256, 256>>>(etype, E);
    offsets_kernel<<<1, 1>>>();
    scatter_types_kernel<<<(E + 255) / 256, 256>>>(etype, E);

    int nWeI = 6 * 4 * 256 * 512, nWeO = 2 * 4 * 512 * 1024;
    int nWdI = 6 * 256 * 256,     nWdO = 2 * 256 * 512;
    conv_f16_kernel<<<(nWeI + 255) / 256, 256>>>(WeI, WeIh, WeIl, nWeI);
    conv_f16_kernel<<<(nWeO + 255) / 256, 256>>>(WeO, WeOh, WeOl, nWeO);
    conv_f16_kernel<<<(nWdI + 255) / 256, 256>>>(WdI, WdIh, WdIl, nWdI);
    conv_f16_kernel<<<(nWdO + 255) / 256, 256>>>(WdO, WdOh, WdOl, nWdO);

    embed_kernel<<<(N * 64 + 255) / 256, 256>>>((const float4*)embed, ids, (float4*)S0,
                                                (uint2*)Sh, N);

    // Buffer dance (no SAVE copy): block-start fp32 lives in S0 for the whole block;
    // inner L1/L2 fp32 outputs are dead (only fp16 twin consumed) -> skipped;
    // inner L3 fp32 -> S1; concat(S0, S1) -> Sh(512); outer fp32 -> S0 (b=0) / out (b=1).
    for (int b = 0; b < 2; b++) {
        for (int i = 0; i < 3; i++) {
            int l = 3 * b + i;
            float* destF = (i == 2) ? S1 : nullptr;
            run_gnn_layer(256, N, E, Sh, Mh,
                          WeIh + (size_t)l * 4 * 256 * 512, WeIl + (size_t)l * 4 * 256 * 512,
                          lsI + (size_t)l * 256, lbI + (size_t)l * 256,
                          WdIh + (size_t)l * 256 * 256, WdIl + (size_t)l * 256 * 256,
                          bdI + (size_t)l * 256,
                          destF, M, Sh, src, tgt);
        }
        concat_f16_kernel<<<(N * 128 + 255) / 256, 256>>>((const float4*)S0,
                                                          (const float4*)S1, Sh, N);
        float* destF = (b == 1) ? out : S0;
        run_gnn_layer(512, N, E, Sh, Mh,
                      WeOh + (size_t)b * 4 * 512 * 1024, WeOl + (size_t)b * 4 * 512 * 1024,
                      lsO + (size_t)b * 512, lbO + (size_t)b * 512,
                      WdOh + (size_t)b * 256 * 512, WdOl + (size_t)b * 256 * 512,
                      bdO + (size_t)b * 256,
                      destF, M,
                      (b == 0) ? Sh : nullptr,
                      src, tgt);
    }
}